// round 5
// baseline (speedup 1.0000x reference)
#include <cuda_runtime.h>
#include <math.h>

#define BB 2
#define SS 1024
#define DM 1024
#define NH 16
#define DH 64
#define MROWS (BB*SS)
#define MAXN 0.996f

__device__ float g_qkv[3][MROWS*DM];
__device__ float g_aux[3][MROWS*NH];   // per-(row,head) final ||y||^2

__device__ __forceinline__ unsigned f2tf32(float x) {
    unsigned r; asm("cvt.rna.tf32.f32 %0, %1;" : "=r"(r) : "f"(x)); return r;
}
__device__ __forceinline__ void mma8(float* d, const unsigned* a, const unsigned* b) {
    asm volatile("mma.sync.aligned.m16n8k8.row.col.f32.tf32.tf32.f32 "
        "{%0,%1,%2,%3}, {%4,%5,%6,%7}, {%8,%9}, {%0,%1,%2,%3};"
        : "+f"(d[0]), "+f"(d[1]), "+f"(d[2]), "+f"(d[3])
        : "r"(a[0]), "r"(a[1]), "r"(a[2]), "r"(a[3]), "r"(b[0]), "r"(b[1]));
}
__device__ __forceinline__ float fsqrt_a(float x){float r;asm("sqrt.approx.f32 %0,%1;":"=f"(r):"f"(x));return r;}
__device__ __forceinline__ float frcp_a (float x){float r;asm("rcp.approx.f32 %0,%1;" :"=f"(r):"f"(x));return r;}
__device__ __forceinline__ float flg2_a (float x){float r;asm("lg2.approx.f32 %0,%1;" :"=f"(r):"f"(x));return r;}
__device__ __forceinline__ float fex2_a (float x){float r;asm("ex2.approx.f32 %0,%1;" :"=f"(r):"f"(x));return r;}

// ---------------------------------------------------------------------------
// Kernel 1: tf32 GEMM, double-buffered smem, fused norms + Poincare epilogue.
// ---------------------------------------------------------------------------
#define GEMM_SMEM_WORDS (2*128*36 + 2*32*136)
__global__ __launch_bounds__(256, 2)
void gemm_proj_kernel(const float* __restrict__ X, const float* __restrict__ qz,
                      const float* __restrict__ kz, const float* __restrict__ vz,
                      const float* __restrict__ qr, const float* __restrict__ kr,
                      const float* __restrict__ vr) {
    int which = blockIdx.z;
    const float* Z = (which == 0) ? qz : (which == 1) ? kz : vz;
    const float* R = (which == 0) ? qr : (which == 1) ? kr : vr;
    float* Cw = g_qkv[which];

    extern __shared__ unsigned gsm[];
    unsigned (*As)[128][36] = (unsigned(*)[128][36])gsm;
    unsigned (*Bs)[32][136] = (unsigned(*)[32][136])(gsm + 2*128*36);

    int t = threadIdx.x;
    int wid = t >> 5, lane = t & 31;
    int L2 = lane >> 2, L0 = lane & 3;
    int wm = wid >> 1, wn = wid & 1;
    int m0 = blockIdx.x * 128, n0 = blockIdx.y * 128;

    float acc[2][8][4] = {};
    float assq[4] = {};
    float bssq[4] = {};
    float4 areg[4], breg[4];

    // prefetch tile 0 + stage into buffer 0
    #pragma unroll
    for (int j = 0; j < 4; j++) {
        int idx = t + j * 256;
        areg[j] = *(const float4*)&X[(m0 + (idx >> 3)) * DM + (idx & 7) * 4];
        breg[j] = *(const float4*)&Z[(idx >> 5) * DM + n0 + (idx & 31) * 4];
    }
    #pragma unroll
    for (int j = 0; j < 4; j++) {
        int idx = t + j * 256;
        float4 v = areg[j];
        assq[j] = fmaf(v.x, v.x, fmaf(v.y, v.y, fmaf(v.z, v.z, fmaf(v.w, v.w, assq[j]))));
        *(uint4*)&As[0][idx >> 3][(idx & 7) * 4] =
            make_uint4(f2tf32(v.x), f2tf32(v.y), f2tf32(v.z), f2tf32(v.w));
        float4 w = breg[j];
        bssq[0] = fmaf(w.x, w.x, bssq[0]); bssq[1] = fmaf(w.y, w.y, bssq[1]);
        bssq[2] = fmaf(w.z, w.z, bssq[2]); bssq[3] = fmaf(w.w, w.w, bssq[3]);
        *(uint4*)&Bs[0][idx >> 5][(idx & 31) * 4] =
            make_uint4(f2tf32(w.x), f2tf32(w.y), f2tf32(w.z), f2tf32(w.w));
    }
    __syncthreads();

    #pragma unroll 1
    for (int kt = 0; kt < 32; kt++) {
        int st = kt & 1;
        if (kt < 31) {
            int k0 = (kt + 1) * 32;
            #pragma unroll
            for (int j = 0; j < 4; j++) {
                int idx = t + j * 256;
                areg[j] = *(const float4*)&X[(m0 + (idx >> 3)) * DM + k0 + (idx & 7) * 4];
                breg[j] = *(const float4*)&Z[(k0 + (idx >> 5)) * DM + n0 + (idx & 31) * 4];
            }
        }
        #pragma unroll
        for (int k8 = 0; k8 < 4; k8++) {
            int kb = k8 * 8 + L0;
            unsigned a[2][4];
            #pragma unroll
            for (int mt = 0; mt < 2; mt++) {
                int r = wm * 32 + mt * 16 + L2;
                a[mt][0] = As[st][r][kb];     a[mt][1] = As[st][r + 8][kb];
                a[mt][2] = As[st][r][kb + 4]; a[mt][3] = As[st][r + 8][kb + 4];
            }
            #pragma unroll
            for (int nt = 0; nt < 8; nt++) {
                int c = wn * 64 + nt * 8 + L2;
                unsigned b[2] = { Bs[st][kb][c], Bs[st][kb + 4][c] };
                mma8(acc[0][nt], a[0], b);
                mma8(acc[1][nt], a[1], b);
            }
        }
        if (kt < 31) {
            int s2 = st ^ 1;
            #pragma unroll
            for (int j = 0; j < 4; j++) {
                int idx = t + j * 256;
                float4 v = areg[j];
                assq[j] = fmaf(v.x, v.x, fmaf(v.y, v.y, fmaf(v.z, v.z, fmaf(v.w, v.w, assq[j]))));
                *(uint4*)&As[s2][idx >> 3][(idx & 7) * 4] =
                    make_uint4(f2tf32(v.x), f2tf32(v.y), f2tf32(v.z), f2tf32(v.w));
                float4 w = breg[j];
                bssq[0] = fmaf(w.x, w.x, bssq[0]); bssq[1] = fmaf(w.y, w.y, bssq[1]);
                bssq[2] = fmaf(w.z, w.z, bssq[2]); bssq[3] = fmaf(w.w, w.w, bssq[3]);
                *(uint4*)&Bs[s2][idx >> 5][(idx & 31) * 4] =
                    make_uint4(f2tf32(w.x), f2tf32(w.y), f2tf32(w.z), f2tf32(w.w));
            }
        }
        __syncthreads();
    }

    // ---- reduce fused norms (partials staged through smem) ----
    float* rowp = (float*)gsm;             // [128][9]
    float* colp = rowp + 1152;             // [32 col4][8 warp] float4
    #pragma unroll
    for (int j = 0; j < 4; j++)
        rowp[(j * 32 + (t >> 3)) * 9 + (t & 7)] = assq[j];
    *(float4*)&colp[(((t & 31) * 8) + (t >> 5)) * 4] = make_float4(bssq[0], bssq[1], bssq[2], bssq[3]);
    __syncthreads();

    float* scA  = (float*)(gsm + 2*128*36);   // 2*cosh(2r)/zn for 128 cols
    float* szn2 = scA + 128;                  // 2*zn
    float* ssh  = szn2 + 128;                 // sinh(2r)
    float* scx  = ssh + 128;                  // ||x_row||^2 for 128 rows
    if (t < 128) {
        float s = 0.f;
        #pragma unroll
        for (int i = 0; i < 8; i++) s += rowp[t * 9 + i];
        scx[t] = s;
        float zs = 0.f;
        #pragma unroll
        for (int i = 0; i < 8; i++) zs += colp[((t >> 2) * 8 + i) * 4 + (t & 3)];
        float zn = fmaxf(fsqrt_a(zs), 1e-15f);
        float rv = 2.0f * R[n0 + t];
        float e  = fex2_a(rv * 1.44269504f);
        float ie = frcp_a(e);
        scA[t]  = (e + ie) * frcp_a(zn);
        szn2[t] = 2.0f * zn;
        ssh[t]  = 0.5f * (e - ie);
    }
    __syncthreads();

    // ---- fused Poincare epilogue ----
    int head = (n0 >> 6) + wn;
    #pragma unroll
    for (int mt = 0; mt < 2; mt++) {
        #pragma unroll
        for (int hh = 0; hh < 2; hh++) {
            int rloc = wm * 32 + mt * 16 + hh * 8 + L2;
            float cx2 = scx[rloc];
            float invden = frcp_a(fmaxf(1.0f - cx2, 1e-15f));
            float opc = 1.0f + cx2;
            float sq = 0.f;
            #pragma unroll
            for (int nt = 0; nt < 8; nt++) {
                int cl = wn * 64 + nt * 8 + 2 * L0;
                #pragma unroll
                for (int u = 0; u < 2; u++) {
                    float xz  = acc[mt][nt][hh * 2 + u];
                    float arg = fmaf(xz, scA[cl + u], -opc * ssh[cl + u]) * invden;
                    float aa  = fabsf(arg);
                    float A   = aa + fsqrt_a(fmaf(aa, aa, 1.0f));
                    float tE  = fex2_a(szn2[cl + u] * flg2_a(A));
                    float y   = copysignf(0.5f * (tE - frcp_a(tE)), arg);
                    acc[mt][nt][hh * 2 + u] = y;
                    sq = fmaf(y, y, sq);
                }
            }
            sq += __shfl_xor_sync(0xffffffffu, sq, 1);
            sq += __shfl_xor_sync(0xffffffffu, sq, 2);
            float n1  = fmaxf(sqrtf(sq), 1e-15f);
            float s1  = (n1 > MAXN) ? (MAXN / n1) : 1.0f;
            float n1c = n1 * s1;
            float f   = 1.0f / (1.0f + sqrtf(1.0f + n1c * n1c));
            float n2  = fmaxf(n1c * f, 1e-15f);
            float s2v = (n2 > MAXN) ? (MAXN / n2) : 1.0f;
            float hs  = s1 * f * s2v;
            float n3  = n2 * s2v;
            int grow = m0 + rloc;
            if (L0 == 0) g_aux[which][grow * NH + head] = n3 * n3;
            #pragma unroll
            for (int nt = 0; nt < 8; nt++) {
                int cl = wn * 64 + nt * 8 + 2 * L0;
                *(float2*)&Cw[grow * DM + n0 + cl] =
                    make_float2(acc[mt][nt][hh * 2] * hs, acc[mt][nt][hh * 2 + 1] * hs);
            }
        }
    }
}

// ---------------------------------------------------------------------------
// Kernel 2: flash-style hyperbolic attention, fragment-major smem layouts.
// w = exp(mask)/((1+tt)+sqrt(tt*(tt+2))) ; unnormalized accumulation
// (weights bounded in (0, e^mask]; softmax is scale-invariant).
//   qf: [rb(8)][k8(8)][lane(32)][4]           A-frags, LDS.128, conflict-free
//   kf/vf: [k8(8) stride 644][lane(32)*20]    B-frags, 4x LDS.128/k8, conflict-free
//   sck: per-key float4 {k2, 1/(1-k2), gamma-1, exp(mask)}
// ---------------------------------------------------------------------------
#define ATT_SMEM_WORDS (8192 + 5152 + 5152 + 128*68 + 256 + 128)
__global__ __launch_bounds__(256, 2)
void attn_kernel(const float* __restrict__ mask, float* __restrict__ out) {
    extern __shared__ unsigned smu[];
    unsigned* qf = smu;                                   // 8192
    unsigned* kf = smu + 8192;                            // 5152
    unsigned* vf = smu + 13344;                           // 5152
    unsigned (*ps)[68] = (unsigned(*)[68])(smu + 18496);  // 128*68
    float4* sck = (float4*)(smu + 18496 + 128*68);        // 64 float4
    float* q2s  = (float*)(smu + 18496 + 128*68 + 256);   // 128

    int bh = blockIdx.x, qt = blockIdx.y;
    int b = bh >> 4, h = bh & 15;
    int t = threadIdx.x, wid = t >> 5, lane = t & 31;
    int L2 = lane >> 2, L0 = lane & 3;
    int qi0 = qt * 128;

    const float* Q = g_qkv[0];
    const float* K = g_qkv[1];
    const float* V = g_qkv[2];

    // ---- Q tile -> fragment-major smem ----
    #pragma unroll
    for (int j = 0; j < 8; j++) {
        int idx = t + j * 256;
        int row = idx >> 4, c4 = (idx & 15) * 4;
        float4 v = *(const float4*)&Q[(b * SS + qi0 + row) * DM + h * DH + c4];
        int rb = row >> 4, rr = row & 15;
        int pos = (rr >> 3) + ((c4 & 4) ? 2 : 0);
        unsigned* qb = qf + ((rb * 8 + (c4 >> 3)) * 32 + (rr & 7) * 4) * 4 + pos;
        qb[0]  = f2tf32(v.x); qb[4]  = f2tf32(v.y);
        qb[8]  = f2tf32(v.z); qb[12] = f2tf32(v.w);
    }
    if (t < 128) q2s[t] = g_aux[0][(b * SS + qi0 + t) * NH + h];
    __syncthreads();

    int rA = wid * 16 + L2;
    float q2_0 = q2s[rA], q2_1 = q2s[rA + 8];
    float tiq0 = 2.0f * frcp_a(fmaxf(1.0f - q2_0, 1e-15f));
    float tiq1 = 2.0f * frcp_a(fmaxf(1.0f - q2_1, 1e-15f));

    float o[8][4] = {};
    float accd0 = 0.f, accd1 = 0.f;

    for (int kt = 0; kt < SS / 64; kt++) {
        int kj0 = kt * 64;
        // ---- K/V tiles -> fragment-major smem ----
        #pragma unroll
        for (int j = 0; j < 4; j++) {
            int idx = t + j * 256;
            int row = idx >> 4, c4 = (idx & 15) * 4;
            int gr = b * SS + kj0 + row;
            float4 kv = *(const float4*)&K[gr * DM + h * DH + c4];
            {   // K: ntk=row>>3, L2k=row&7, k8=c4>>3, p=(c4&4)?1:0, L0=i
                unsigned* kb = kf + (c4 >> 3) * 644 + ((row & 7) * 4) * 20
                             + (row >> 3) * 2 + ((c4 & 4) ? 1 : 0);
                kb[0]  = f2tf32(kv.x); kb[20] = f2tf32(kv.y);
                kb[40] = f2tf32(kv.z); kb[60] = f2tf32(kv.w);
            }
            float v2 = g_aux[2][gr * NH + h];
            float gam = 2.0f * frcp_a(fmaxf(1.0f - v2, 1e-15f));
            float4 vv = *(const float4*)&V[gr * DM + h * DH + c4];
            {   // V: k8v=row>>3, L0v=row&3, pv=(row&4)?1:0, nt=c4>>3, L2v=(c4&4)+i
                unsigned* vb = vf + (row >> 3) * 644 + (((c4 & 4) * 4) + (row & 3)) * 20
                             + (c4 >> 3) * 2 + ((row & 4) ? 1 : 0);
                vb[0]   = f2tf32(vv.x * gam); vb[80]  = f2tf32(vv.y * gam);
                vb[160] = f2tf32(vv.z * gam); vb[240] = f2tf32(vv.w * gam);
            }
        }
        if (t < 64) {
            int gr = b * SS + kj0 + t;
            float k2 = g_aux[1][gr * NH + h];
            float v2 = g_aux[2][gr * NH + h];
            sck[t] = make_float4(k2, frcp_a(fmaxf(1.0f - k2, 1e-15f)),
                                 2.0f * frcp_a(fmaxf(1.0f - v2, 1e-15f)) - 1.0f,
                                 __expf(mask[b * SS + kj0 + t]));
        }
        __syncthreads();

        // ---- QK^T (fragment loads: 1x LDS.128 A + 4x LDS.128 B per k8) ----
        float s[8][4] = {};
        #pragma unroll
        for (int k8 = 0; k8 < 8; k8++) {
            uint4 af = *(uint4*)&qf[((wid * 8 + k8) * 32 + lane) * 4];
            unsigned a[4] = { af.x, af.y, af.z, af.w };
            unsigned kv16[16];
            const unsigned* kbase = kf + k8 * 644 + lane * 20;
            *(uint4*)&kv16[0]  = *(const uint4*)&kbase[0];
            *(uint4*)&kv16[4]  = *(const uint4*)&kbase[4];
            *(uint4*)&kv16[8]  = *(const uint4*)&kbase[8];
            *(uint4*)&kv16[12] = *(const uint4*)&kbase[12];
            #pragma unroll
            for (int nt = 0; nt < 8; nt++) mma8(s[nt], a, &kv16[nt * 2]);
        }

        // ---- score -> weight, accumulate denominator, stage P ----
        #pragma unroll
        for (int nt = 0; nt < 8; nt++) {
            int j0 = nt * 8 + 2 * L0;
            float4 c0 = sck[j0], c1 = sck[j0 + 1];
            float w[4];
            #pragma unroll
            for (int e = 0; e < 4; e++) {
                float q2v = (e < 2) ? q2_0 : q2_1;
                float cc  = ((e < 2) ? tiq0 : tiq1) * ((e & 1) ? c1.y : c0.y);
                float k2v = (e & 1) ? c1.x : c0.x;
                float emv = (e & 1) ? c1.w : c0.w;
                float num = fmaxf(fmaf(-2.0f, s[nt][e], q2v + k2v), 1e-15f);
                float tt  = num * cc;
                float sr  = fsqrt_a(tt * (tt + 2.0f));
                w[e] = __fdividef(emv, (1.0f + tt) + sr);
            }
            accd0 = fmaf(w[0], c0.z, fmaf(w[1], c1.z, accd0));
            accd1 = fmaf(w[2], c0.z, fmaf(w[3], c1.z, accd1));
            *(uint2*)&ps[rA][j0]     = make_uint2(f2tf32(w[0]), f2tf32(w[1]));
            *(uint2*)&ps[rA + 8][j0] = make_uint2(f2tf32(w[2]), f2tf32(w[3]));
        }
        __syncwarp();

        // ---- P @ (gamma V) ----
        #pragma unroll
        for (int k8 = 0; k8 < 8; k8++) {
            int kb = k8 * 8 + L0;
            unsigned a[4] = { ps[rA][kb], ps[rA + 8][kb], ps[rA][kb + 4], ps[rA + 8][kb + 4] };
            unsigned vv16[16];
            const unsigned* vbase = vf + k8 * 644 + lane * 20;
            *(uint4*)&vv16[0]  = *(const uint4*)&vbase[0];
            *(uint4*)&vv16[4]  = *(const uint4*)&vbase[4];
            *(uint4*)&vv16[8]  = *(const uint4*)&vbase[8];
            *(uint4*)&vv16[12] = *(const uint4*)&vbase[12];
            #pragma unroll
            for (int nt = 0; nt < 8; nt++) mma8(o[nt], a, &vv16[nt * 2]);
        }
        __syncthreads();
    }

    // ---- finalize: gyromidpoint + project ----
    accd0 += __shfl_xor_sync(0xffffffffu, accd0, 1);
    accd0 += __shfl_xor_sync(0xffffffffu, accd0, 2);
    accd1 += __shfl_xor_sync(0xffffffffu, accd1, 1);
    accd1 += __shfl_xor_sync(0xffffffffu, accd1, 2);
    #pragma unroll
    for (int rh = 0; rh < 2; rh++) {
        float accd = rh ? accd1 : accd0;
        float invd = 1.0f / fmaxf(accd, 1e-10f);
        float tm[8][2];
        float sq = 0.f;
        #pragma unroll
        for (int nt = 0; nt < 8; nt++) {
            tm[nt][0] = o[nt][rh * 2 + 0] * invd;
            tm[nt][1] = o[nt][rh * 2 + 1] * invd;
            sq += tm[nt][0] * tm[nt][0] + tm[nt][1] * tm[nt][1];
        }
        sq += __shfl_xor_sync(0xffffffffu, sq, 1);
        sq += __shfl_xor_sync(0xffffffffu, sq, 2);
        float f = 1.0f / (1.0f + sqrtf(fmaxf(1.0f - sq, 1e-15f)));
        float n = fmaxf(sqrtf(sq) * f, 1e-15f);
        float s2 = (n > MAXN) ? (MAXN / n) : 1.0f;
        float g = f * s2;
        int qrow = qi0 + rA + rh * 8;
        #pragma unroll
        for (int nt = 0; nt < 8; nt++) {
            *(float2*)&out[(b * SS + qrow) * DM + h * DH + nt * 8 + 2 * L0] =
                make_float2(tm[nt][0] * g, tm[nt][1] * g);
        }
    }
}

// ---------------------------------------------------------------------------
extern "C" void kernel_launch(void* const* d_in, const int* in_sizes, int n_in,
                              void* d_out, int out_size) {
    const float* hidden = (const float*)d_in[0];
    const float* amask  = (const float*)d_in[1];
    const float* qz = (const float*)d_in[2];
    const float* qr = (const float*)d_in[3];
    const float* kz = (const float*)d_in[4];
    const float* kr = (const float*)d_in[5];
    const float* vz = (const float*)d_in[6];
    const float* vr = (const float*)d_in[7];
    float* out = (float*)d_out;

    static bool attr_done = false;
    if (!attr_done) {
        cudaFuncSetAttribute(attn_kernel, cudaFuncAttributeMaxDynamicSharedMemorySize,
                             ATT_SMEM_WORDS * 4);
        cudaFuncSetAttribute(gemm_proj_kernel, cudaFuncAttributeMaxDynamicSharedMemorySize,
                             GEMM_SMEM_WORDS * 4);
        attr_done = true;
    }

    gemm_proj_kernel<<<dim3(MROWS / 128, DM / 128, 3), 256, GEMM_SMEM_WORDS * 4>>>(
        hidden, qz, kz, vz, qr, kr, vr);
    attn_kernel<<<dim3(BB * NH, SS / 128), 256, ATT_SMEM_WORDS * 4>>>(amask, out);
}

// round 7
// speedup vs baseline: 1.0876x; 1.0876x over previous
#include <cuda_runtime.h>
#include <math.h>

#define BB 2
#define SS 1024
#define DM 1024
#define NH 16
#define DH 64
#define MROWS (BB*SS)
#define MAXN 0.996f

__device__ float g_qkv[3][MROWS*DM];
__device__ float g_aux[3][MROWS*NH];        // per-(row,head) final ||y||^2
__device__ unsigned g_kfrag[32*16*8*512];   // K  mma-frag order, 8MB
__device__ unsigned g_vfrag[32*16*8*512];   // gamma*V mma-frag order, 8MB
__device__ float4   g_sck[32*1024];         // per (bh,key): {k2, 1/(1-k2), gm1, e^mask}

__device__ __forceinline__ unsigned f2tf32(float x) {
    unsigned r; asm("cvt.rna.tf32.f32 %0, %1;" : "=r"(r) : "f"(x)); return r;
}
__device__ __forceinline__ void mma8(float* d, const unsigned* a, const unsigned* b) {
    asm volatile("mma.sync.aligned.m16n8k8.row.col.f32.tf32.tf32.f32 "
        "{%0,%1,%2,%3}, {%4,%5,%6,%7}, {%8,%9}, {%0,%1,%2,%3};"
        : "+f"(d[0]), "+f"(d[1]), "+f"(d[2]), "+f"(d[3])
        : "r"(a[0]), "r"(a[1]), "r"(a[2]), "r"(a[3]), "r"(b[0]), "r"(b[1]));
}
__device__ __forceinline__ float fsqrt_a(float x){float r;asm("sqrt.approx.f32 %0,%1;":"=f"(r):"f"(x));return r;}
__device__ __forceinline__ float frcp_a (float x){float r;asm("rcp.approx.f32 %0,%1;" :"=f"(r):"f"(x));return r;}
__device__ __forceinline__ float flg2_a (float x){float r;asm("lg2.approx.f32 %0,%1;" :"=f"(r):"f"(x));return r;}
__device__ __forceinline__ float fex2_a (float x){float r;asm("ex2.approx.f32 %0,%1;" :"=f"(r):"f"(x));return r;}

// ---------------------------------------------------------------------------
// Kernel 1: tf32 GEMM + fused norms + Poincare epilogue (R4 proven version)
// ---------------------------------------------------------------------------
__global__ __launch_bounds__(256, 2)
void gemm_proj_kernel(const float* __restrict__ X, const float* __restrict__ qz,
                      const float* __restrict__ kz, const float* __restrict__ vz,
                      const float* __restrict__ qr, const float* __restrict__ kr,
                      const float* __restrict__ vr) {
    int which = blockIdx.z;
    const float* Z = (which == 0) ? qz : (which == 1) ? kz : vz;
    const float* R = (which == 0) ? qr : (which == 1) ? kr : vr;
    float* Cw = g_qkv[which];

    __shared__ unsigned As[128][36];
    __shared__ unsigned Bs[32][136];

    int t = threadIdx.x;
    int wid = t >> 5, lane = t & 31;
    int L2 = lane >> 2, L0 = lane & 3;
    int wm = wid >> 1, wn = wid & 1;
    int m0 = blockIdx.x * 128, n0 = blockIdx.y * 128;

    float acc[2][8][4] = {};
    float assq[4] = {};
    float bssq[4] = {};

    for (int k0 = 0; k0 < DM; k0 += 32) {
        #pragma unroll
        for (int j = 0; j < 4; j++) {
            int idx = t + j * 256;
            int m = idx >> 3, kc = (idx & 7) * 4;
            float4 v = *(const float4*)&X[(m0 + m) * DM + k0 + kc];
            assq[j] = fmaf(v.x, v.x, fmaf(v.y, v.y, fmaf(v.z, v.z, fmaf(v.w, v.w, assq[j]))));
            *(uint4*)&As[m][kc] = make_uint4(f2tf32(v.x), f2tf32(v.y), f2tf32(v.z), f2tf32(v.w));
        }
        #pragma unroll
        for (int j = 0; j < 4; j++) {
            int idx = t + j * 256;
            int kk = idx >> 5, nn = (idx & 31) * 4;
            float4 v = *(const float4*)&Z[(k0 + kk) * DM + n0 + nn];
            bssq[0] = fmaf(v.x, v.x, bssq[0]); bssq[1] = fmaf(v.y, v.y, bssq[1]);
            bssq[2] = fmaf(v.z, v.z, bssq[2]); bssq[3] = fmaf(v.w, v.w, bssq[3]);
            *(uint4*)&Bs[kk][nn] = make_uint4(f2tf32(v.x), f2tf32(v.y), f2tf32(v.z), f2tf32(v.w));
        }
        __syncthreads();
        #pragma unroll
        for (int k8 = 0; k8 < 4; k8++) {
            int kb = k8 * 8 + L0;
            unsigned a[2][4];
            #pragma unroll
            for (int mt = 0; mt < 2; mt++) {
                int r = wm * 32 + mt * 16 + L2;
                a[mt][0] = As[r][kb];     a[mt][1] = As[r + 8][kb];
                a[mt][2] = As[r][kb + 4]; a[mt][3] = As[r + 8][kb + 4];
            }
            #pragma unroll
            for (int nt = 0; nt < 8; nt++) {
                int c = wn * 64 + nt * 8 + L2;
                unsigned b[2] = { Bs[kb][c], Bs[kb + 4][c] };
                mma8(acc[0][nt], a[0], b);
                mma8(acc[1][nt], a[1], b);
            }
        }
        __syncthreads();
    }

    float* rowp = (float*)As;
    float* colp = rowp + 1152;
    #pragma unroll
    for (int j = 0; j < 4; j++)
        rowp[(j * 32 + (t >> 3)) * 9 + (t & 7)] = assq[j];
    *(float4*)&colp[(((t & 31) * 8) + (t >> 5)) * 4] = make_float4(bssq[0], bssq[1], bssq[2], bssq[3]);
    __syncthreads();

    float* scA  = (float*)Bs;
    float* szn2 = scA + 128;
    float* ssh  = szn2 + 128;
    float* scx  = ssh + 128;
    if (t < 128) {
        float s = 0.f;
        #pragma unroll
        for (int i = 0; i < 8; i++) s += rowp[t * 9 + i];
        scx[t] = s;
        float zs = 0.f;
        #pragma unroll
        for (int i = 0; i < 8; i++) zs += colp[((t >> 2) * 8 + i) * 4 + (t & 3)];
        float zn = fmaxf(fsqrt_a(zs), 1e-15f);
        float rv = 2.0f * R[n0 + t];
        float e  = fex2_a(rv * 1.44269504f);
        float ie = frcp_a(e);
        scA[t]  = (e + ie) * frcp_a(zn);
        szn2[t] = 2.0f * zn;
        ssh[t]  = 0.5f * (e - ie);
    }
    __syncthreads();

    int head = (n0 >> 6) + wn;
    #pragma unroll
    for (int mt = 0; mt < 2; mt++) {
        #pragma unroll
        for (int hh = 0; hh < 2; hh++) {
            int rloc = wm * 32 + mt * 16 + hh * 8 + L2;
            float cx2 = scx[rloc];
            float invden = frcp_a(fmaxf(1.0f - cx2, 1e-15f));
            float opc = 1.0f + cx2;
            float sq = 0.f;
            #pragma unroll
            for (int nt = 0; nt < 8; nt++) {
                int cl = wn * 64 + nt * 8 + 2 * L0;
                #pragma unroll
                for (int u = 0; u < 2; u++) {
                    float xz  = acc[mt][nt][hh * 2 + u];
                    float arg = fmaf(xz, scA[cl + u], -opc * ssh[cl + u]) * invden;
                    float aa  = fabsf(arg);
                    float A   = aa + fsqrt_a(fmaf(aa, aa, 1.0f));
                    float tE  = fex2_a(szn2[cl + u] * flg2_a(A));
                    float y   = copysignf(0.5f * (tE - frcp_a(tE)), arg);
                    acc[mt][nt][hh * 2 + u] = y;
                    sq = fmaf(y, y, sq);
                }
            }
            sq += __shfl_xor_sync(0xffffffffu, sq, 1);
            sq += __shfl_xor_sync(0xffffffffu, sq, 2);
            float n1  = fmaxf(sqrtf(sq), 1e-15f);
            float s1  = (n1 > MAXN) ? (MAXN / n1) : 1.0f;
            float n1c = n1 * s1;
            float f   = 1.0f / (1.0f + sqrtf(1.0f + n1c * n1c));
            float n2  = fmaxf(n1c * f, 1e-15f);
            float s2v = (n2 > MAXN) ? (MAXN / n2) : 1.0f;
            float hs  = s1 * f * s2v;
            float n3  = n2 * s2v;
            int grow = m0 + rloc;
            if (L0 == 0) g_aux[which][grow * NH + head] = n3 * n3;
            #pragma unroll
            for (int nt = 0; nt < 8; nt++) {
                int cl = wn * 64 + nt * 8 + 2 * L0;
                *(float2*)&Cw[grow * DM + n0 + cl] =
                    make_float2(acc[mt][nt][hh * 2] * hs, acc[mt][nt][hh * 2 + 1] * hs);
            }
        }
    }
}

// ---------------------------------------------------------------------------
// Kernel 2: one-shot fragment prep. Converts K and gamma*V into mma-fragment
// global layout + per-key scalar float4. grid (32 bh, 16 ktile), 256 threads.
// Frag layout per (bh,kt,k8): 512 uints = [i4(4)][lane(32)][4] (coalesced).
// ---------------------------------------------------------------------------
__global__ __launch_bounds__(256)
void frag_prep_kernel(const float* __restrict__ mask) {
    __shared__ float Ks[64][68];
    __shared__ float Vs[64][68];

    int bh = blockIdx.x, kt = blockIdx.y;
    int b = bh >> 4, h = bh & 15;
    int kj0 = kt * 64;
    int t = threadIdx.x, lane = t & 31;
    int L2 = lane >> 2, L0 = lane & 3;
    int k8 = t >> 5;

    const float* K = g_qkv[1];
    const float* V = g_qkv[2];

    #pragma unroll
    for (int j = 0; j < 4; j++) {
        int idx = t + j * 256;
        int row = idx >> 4, c4 = (idx & 15) * 4;
        int gr = b * SS + kj0 + row;
        *(float4*)&Ks[row][c4] = *(const float4*)&K[gr * DM + h * DH + c4];
        float v2 = g_aux[2][gr * NH + h];
        float gam = 2.0f * frcp_a(fmaxf(1.0f - v2, 1e-15f));
        float4 vv = *(const float4*)&V[gr * DM + h * DH + c4];
        *(float4*)&Vs[row][c4] = make_float4(vv.x * gam, vv.y * gam, vv.z * gam, vv.w * gam);
    }
    if (t < 64) {
        int gr = b * SS + kj0 + t;
        float k2 = g_aux[1][gr * NH + h];
        float v2 = g_aux[2][gr * NH + h];
        g_sck[bh * 1024 + kj0 + t] =
            make_float4(k2, frcp_a(fmaxf(1.0f - k2, 1e-15f)),
                        2.0f * frcp_a(fmaxf(1.0f - v2, 1e-15f)) - 1.0f,
                        __expf(mask[b * SS + kj0 + t]));
    }
    __syncthreads();

    unsigned wk[16], wv[16];
    #pragma unroll
    for (int nt = 0; nt < 8; nt++) {
        wk[2*nt]   = f2tf32(Ks[nt * 8 + L2][k8 * 8 + L0]);
        wk[2*nt+1] = f2tf32(Ks[nt * 8 + L2][k8 * 8 + L0 + 4]);
        wv[2*nt]   = f2tf32(Vs[k8 * 8 + L0][nt * 8 + L2]);
        wv[2*nt+1] = f2tf32(Vs[k8 * 8 + L0 + 4][nt * 8 + L2]);
    }
    unsigned base = (((unsigned)(bh * 16 + kt) * 8) + k8) * 512 + lane * 4;
    #pragma unroll
    for (int i4 = 0; i4 < 4; i4++) {
        *(uint4*)&g_kfrag[base + i4 * 128] = ((uint4*)wk)[i4];
        *(uint4*)&g_vfrag[base + i4 * 128] = ((uint4*)wv)[i4];
    }
}

// ---------------------------------------------------------------------------
// Kernel 3: flash-style hyperbolic attention. B-operands stream directly from
// pre-converted global fragments (coalesced LDG.128, L1/L2-resident).
// No per-tile conversion, no __syncthreads in the main loop (warps free-run;
// ps and scalar staging are warp-private).
// ---------------------------------------------------------------------------
#define ATT_SMEM_WORDS (8192 + 128*68 + 8*64*4 + 128)
__global__ __launch_bounds__(256, 2)
void attn_kernel(float* __restrict__ out) {
    extern __shared__ unsigned smu[];
    unsigned* qf = smu;                                  // 8192: Q frags
    unsigned (*ps)[68] = (unsigned(*)[68])(smu + 8192);  // 128x68 P staging
    float4* sws = (float4*)(smu + 8192 + 128*68);        // per-warp 64 float4
    float* q2s  = (float*)(smu + 8192 + 128*68 + 8*64*4);

    int bh = blockIdx.x, qt = blockIdx.y;
    int b = bh >> 4, h = bh & 15;
    int t = threadIdx.x, wid = t >> 5, lane = t & 31;
    int L2 = lane >> 2, L0 = lane & 3;
    int qi0 = qt * 128;

    const float* Q = g_qkv[0];

    // ---- Q tile -> fragment-major smem (one-time) ----
    #pragma unroll
    for (int j = 0; j < 8; j++) {
        int idx = t + j * 256;
        int row = idx >> 4, c4 = (idx & 15) * 4;
        float4 v = *(const float4*)&Q[(b * SS + qi0 + row) * DM + h * DH + c4];
        int rb = row >> 4, rr = row & 15;
        int pos = (rr >> 3) + ((c4 & 4) ? 2 : 0);
        unsigned* qb = qf + ((rb * 8 + (c4 >> 3)) * 32 + (rr & 7) * 4) * 4 + pos;
        qb[0]  = f2tf32(v.x); qb[4]  = f2tf32(v.y);
        qb[8]  = f2tf32(v.z); qb[12] = f2tf32(v.w);
    }
    if (t < 128) q2s[t] = g_aux[0][(b * SS + qi0 + t) * NH + h];
    __syncthreads();

    int rA = wid * 16 + L2;
    float q2_0 = q2s[rA], q2_1 = q2s[rA + 8];
    float tiq0 = 2.0f * frcp_a(fmaxf(1.0f - q2_0, 1e-15f));
    float tiq1 = 2.0f * frcp_a(fmaxf(1.0f - q2_1, 1e-15f));

    float4* swsW = sws + wid * 64;
    const float4* sckB = g_sck + bh * 1024;

    float o[8][4] = {};
    float accd0 = 0.f, accd1 = 0.f;

    for (int kt = 0; kt < SS / 64; kt++) {
        int kj0 = kt * 64;
        const unsigned* fbase = (const unsigned*)0 + ((unsigned)(bh * 16 + kt) * 8) * 512 + lane * 4;
        const unsigned* kfb = g_kfrag + (size_t)(fbase - (const unsigned*)0);
        const unsigned* vfb = g_vfrag + (size_t)(fbase - (const unsigned*)0);

        // stage per-key scalars (warp-private)
        swsW[lane * 2]     = sckB[kj0 + lane * 2];
        swsW[lane * 2 + 1] = sckB[kj0 + lane * 2 + 1];
        __syncwarp();

        // ---- QK^T: A from smem (1 LDS.128), B from global (4 LDG.128) per k8
        float s[8][4] = {};
        #pragma unroll
        for (int k8 = 0; k8 < 8; k8++) {
            uint4 af = *(uint4*)&qf[((wid * 8 + k8) * 32 + lane) * 4];
            unsigned a[4] = { af.x, af.y, af.z, af.w };
            unsigned kw[16];
            #pragma unroll
            for (int i4 = 0; i4 < 4; i4++)
                *(uint4*)&kw[i4 * 4] = *(const uint4*)&kfb[k8 * 512 + i4 * 128];
            #pragma unroll
            for (int nt = 0; nt < 8; nt++) mma8(s[nt], a, &kw[nt * 2]);
        }

        // ---- score -> weight, accumulate denominator, stage P ----
        #pragma unroll
        for (int nt = 0; nt < 8; nt++) {
            int j0 = nt * 8 + 2 * L0;
            float4 c0 = swsW[j0], c1 = swsW[j0 + 1];
            float w[4];
            #pragma unroll
            for (int e = 0; e < 4; e++) {
                float q2v = (e < 2) ? q2_0 : q2_1;
                float cc  = ((e < 2) ? tiq0 : tiq1) * ((e & 1) ? c1.y : c0.y);
                float k2v = (e & 1) ? c1.x : c0.x;
                float emv = (e & 1) ? c1.w : c0.w;
                float num = fmaxf(fmaf(-2.0f, s[nt][e], q2v + k2v), 1e-15f);
                float tt  = num * cc;
                float sr  = fsqrt_a(tt * (tt + 2.0f));
                w[e] = __fdividef(emv, (1.0f + tt) + sr);
            }
            accd0 = fmaf(w[0], c0.z, fmaf(w[1], c1.z, accd0));
            accd1 = fmaf(w[2], c0.z, fmaf(w[3], c1.z, accd1));
            *(uint2*)&ps[rA][j0]     = make_uint2(f2tf32(w[0]), f2tf32(w[1]));
            *(uint2*)&ps[rA + 8][j0] = make_uint2(f2tf32(w[2]), f2tf32(w[3]));
        }
        __syncwarp();

        // ---- P @ (gamma V): A from ps, B from global frags ----
        #pragma unroll
        for (int k8 = 0; k8 < 8; k8++) {
            int kb = k8 * 8 + L0;
            unsigned a[4] = { ps[rA][kb], ps[rA + 8][kb], ps[rA][kb + 4], ps[rA + 8][kb + 4] };
            unsigned vw[16];
            #pragma unroll
            for (int i4 = 0; i4 < 4; i4++)
                *(uint4*)&vw[i4 * 4] = *(const uint4*)&vfb[k8 * 512 + i4 * 128];
            #pragma unroll
            for (int nt = 0; nt < 8; nt++) mma8(o[nt], a, &vw[nt * 2]);
        }
        __syncwarp();
    }

    // ---- finalize: gyromidpoint + project ----
    accd0 += __shfl_xor_sync(0xffffffffu, accd0, 1);
    accd0 += __shfl_xor_sync(0xffffffffu, accd0, 2);
    accd1 += __shfl_xor_sync(0xffffffffu, accd1, 1);
    accd1 += __shfl_xor_sync(0xffffffffu, accd1, 2);
    #pragma unroll
    for (int rh = 0; rh < 2; rh++) {
        float accd = rh ? accd1 : accd0;
        float invd = 1.0f / fmaxf(accd, 1e-10f);
        float tm[8][2];
        float sq = 0.f;
        #pragma unroll
        for (int nt = 0; nt < 8; nt++) {
            tm[nt][0] = o[nt][rh * 2 + 0] * invd;
            tm[nt][1] = o[nt][rh * 2 + 1] * invd;
            sq += tm[nt][0] * tm[nt][0] + tm[nt][1] * tm[nt][1];
        }
        sq += __shfl_xor_sync(0xffffffffu, sq, 1);
        sq += __shfl_xor_sync(0xffffffffu, sq, 2);
        float f = 1.0f / (1.0f + sqrtf(fmaxf(1.0f - sq, 1e-15f)));
        float n = fmaxf(sqrtf(sq) * f, 1e-15f);
        float s2 = (n > MAXN) ? (MAXN / n) : 1.0f;
        float g = f * s2;
        int qrow = qi0 + rA + rh * 8;
        #pragma unroll
        for (int nt = 0; nt < 8; nt++) {
            *(float2*)&out[(b * SS + qrow) * DM + h * DH + nt * 8 + 2 * L0] =
                make_float2(tm[nt][0] * g, tm[nt][1] * g);
        }
    }
}

// ---------------------------------------------------------------------------
extern "C" void kernel_launch(void* const* d_in, const int* in_sizes, int n_in,
                              void* d_out, int out_size) {
    const float* hidden = (const float*)d_in[0];
    const float* amask  = (const float*)d_in[1];
    const float* qz = (const float*)d_in[2];
    const float* qr = (const float*)d_in[3];
    const float* kz = (const float*)d_in[4];
    const float* kr = (const float*)d_in[5];
    const float* vz = (const float*)d_in[6];
    const float* vr = (const float*)d_in[7];
    float* out = (float*)d_out;

    static bool attr_done = false;
    if (!attr_done) {
        cudaFuncSetAttribute(attn_kernel, cudaFuncAttributeMaxDynamicSharedMemorySize,
                             ATT_SMEM_WORDS * 4);
        attr_done = true;
    }

    gemm_proj_kernel<<<dim3(MROWS / 128, DM / 128, 3), 256>>>(hidden, qz, kz, vz, qr, kr, vr);
    frag_prep_kernel<<<dim3(32, 16), 256>>>(amask);
    attn_kernel<<<dim3(BB * NH, SS / 128), 256, ATT_SMEM_WORDS * 4>>>(out);
}